// round 2
// baseline (speedup 1.0000x reference)
#include <cuda_runtime.h>

// Problem constants
#define NQ 8192     // query tokens
#define MM 8192     // memory size
#define HD 5120     // hidden
#define PD 1280     // projected dim
#define ED 128      // experts

typedef unsigned long long ull;

// ---------------- scratch (allocation-free: __device__ globals) -------------
__device__ float g_proj[(NQ + MM) * (size_t)PD];   // [16384, 1280] q rows then kp rows
__device__ float g_norm[NQ + MM];                  // squared row norms
__device__ float g_d2[(size_t)NQ * MM];            // [8192, 8192] squared distances

// ---------------- packed f32x2 helpers --------------------------------------
__device__ __forceinline__ void fma2(ull& d, ull a, ull b) {
    asm("fma.rn.f32x2 %0, %1, %2, %0;" : "+l"(d) : "l"(a), "l"(b));
}
__device__ __forceinline__ ull pack2(float x, float y) {
    ull r; asm("mov.b64 %0, {%1, %2};" : "=l"(r) : "f"(x), "f"(y)); return r;
}
__device__ __forceinline__ void unpack2(ull v, float& lo, float& hi) {
    asm("mov.b64 {%0, %1}, %2;" : "=f"(lo), "=f"(hi) : "l"(v));
}

// ---------------- 128x128x8 fp32 SGEMM (NT: both operands K-contiguous) -----
// C[i,j] = sum_k A[i,k]*B[j,k]; DIST=1 epilogue: C = nA[i] + nB[j] - 2*dot
template <int DIST>
__global__ __launch_bounds__(256, 2)
void sgemm_nt(const float* __restrict__ A, const float* __restrict__ B,
              float* __restrict__ C, int K, int ldc,
              const float* __restrict__ nA, const float* __restrict__ nB)
{
    __shared__ float As[2][8][128];
    __shared__ float Bs[2][8][128];

    const int tid  = threadIdx.x;
    const int brow = blockIdx.y * 128;
    const int bcol = blockIdx.x * 128;

    // global tile load mapping: 256 threads x float4 = 128x8 tile
    const int lr = tid >> 1;
    const int lc = (tid & 1) * 4;
    const float* Ag = A + (size_t)(brow + lr) * K + lc;
    const float* Bg = B + (size_t)(bcol + lr) * K + lc;

    // 8x8 micro-tile mapping
    const int tx = tid & 15;
    const int ty = tid >> 4;
    const int r0 = ty * 4;     // rows r0..r0+3 and r0+64..r0+67
    const int c0 = tx * 4;     // cols c0..c0+3 and c0+64..c0+67

    ull acc[8][4];
#pragma unroll
    for (int i = 0; i < 8; i++)
#pragma unroll
        for (int j = 0; j < 4; j++) acc[i][j] = 0ull;

    const int nkt = K >> 3;

    // preload tile 0
    float4 a4 = *(const float4*)Ag;
    float4 b4 = *(const float4*)Bg;
    As[0][lc + 0][lr] = a4.x; As[0][lc + 1][lr] = a4.y;
    As[0][lc + 2][lr] = a4.z; As[0][lc + 3][lr] = a4.w;
    Bs[0][lc + 0][lr] = b4.x; Bs[0][lc + 1][lr] = b4.y;
    Bs[0][lc + 2][lr] = b4.z; Bs[0][lc + 3][lr] = b4.w;
    __syncthreads();

    for (int kt = 0; kt < nkt; ++kt) {
        const int buf = kt & 1;
        if (kt + 1 < nkt) {
            a4 = *(const float4*)(Ag + (size_t)(kt + 1) * 8);
            b4 = *(const float4*)(Bg + (size_t)(kt + 1) * 8);
        }
#pragma unroll
        for (int kk = 0; kk < 8; ++kk) {
            float4 av0 = *(const float4*)&As[buf][kk][r0];
            float4 av1 = *(const float4*)&As[buf][kk][r0 + 64];
            ulonglong2 bq0 = *(const ulonglong2*)&Bs[buf][kk][c0];
            ulonglong2 bq1 = *(const ulonglong2*)&Bs[buf][kk][c0 + 64];
            float a_s[8] = {av0.x, av0.y, av0.z, av0.w, av1.x, av1.y, av1.z, av1.w};
#pragma unroll
            for (int i = 0; i < 8; i++) {
                ull ap = pack2(a_s[i], a_s[i]);
                fma2(acc[i][0], ap, bq0.x);
                fma2(acc[i][1], ap, bq0.y);
                fma2(acc[i][2], ap, bq1.x);
                fma2(acc[i][3], ap, bq1.y);
            }
        }
        if (kt + 1 < nkt) {
            const int nb = buf ^ 1;
            As[nb][lc + 0][lr] = a4.x; As[nb][lc + 1][lr] = a4.y;
            As[nb][lc + 2][lr] = a4.z; As[nb][lc + 3][lr] = a4.w;
            Bs[nb][lc + 0][lr] = b4.x; Bs[nb][lc + 1][lr] = b4.y;
            Bs[nb][lc + 2][lr] = b4.z; Bs[nb][lc + 3][lr] = b4.w;
            __syncthreads();
        }
    }

    // epilogue
#pragma unroll
    for (int i = 0; i < 8; i++) {
        const int gr = brow + ((i < 4) ? (r0 + i) : (r0 + 60 + i));
        float na = 0.f;
        if (DIST) na = nA[gr];
#pragma unroll
        for (int j = 0; j < 4; j++) {
            const int gc = bcol + ((j < 2) ? (c0 + 2 * j) : (c0 + 64 + 2 * (j - 2)));
            float lo, hi;
            unpack2(acc[i][j], lo, hi);
            if (DIST) {
                float2 nb2 = *(const float2*)&nB[gc];
                lo = na + nb2.x - 2.f * lo;
                hi = na + nb2.y - 2.f * hi;
            }
            *(float2*)&C[(size_t)gr * ldc + gc] = make_float2(lo, hi);
        }
    }
}

// ---------------- squared row norms -----------------------------------------
__global__ void row_norms(const float* __restrict__ X, float* __restrict__ nrm)
{
    const int row = blockIdx.x;
    const float4* p = (const float4*)(X + (size_t)row * PD);
    float s = 0.f;
    for (int i = threadIdx.x; i < PD / 4; i += blockDim.x) {
        float4 v = p[i];
        s += v.x * v.x + v.y * v.y + v.z * v.z + v.w * v.w;
    }
#pragma unroll
    for (int o = 16; o; o >>= 1) s += __shfl_down_sync(0xffffffffu, s, o);
    __shared__ float red[4];
    if ((threadIdx.x & 31) == 0) red[threadIdx.x >> 5] = s;
    __syncthreads();
    if (threadIdx.x == 0) nrm[row] = red[0] + red[1] + red[2] + red[3];
}

// ---------------- top-3 + softmax + gather-weighted-sum ---------------------
struct T3 { float d0, d1, d2; int i0, i1, i2; };

__device__ __forceinline__ void t3_ins(T3& t, float d, int m)
{
    if (d < t.d2) {
        if (d < t.d1) {
            t.d2 = t.d1; t.i2 = t.i1;
            if (d < t.d0) { t.d1 = t.d0; t.i1 = t.i0; t.d0 = d; t.i0 = m; }
            else          { t.d1 = d;    t.i1 = m; }
        } else {
            t.d2 = d; t.i2 = m;
        }
    }
}

__global__ __launch_bounds__(256)
void topk_out(const float* __restrict__ D2, const float* __restrict__ V,
              float* __restrict__ out)
{
    const int n = blockIdx.x;
    const float* drow = D2 + (size_t)n * MM;

    T3 t;
    t.d0 = t.d1 = t.d2 = 1e30f;
    t.i0 = t.i1 = t.i2 = 0;
    for (int m = threadIdx.x; m < MM; m += 256) t3_ins(t, drow[m], m);

    // warp tree-merge of sorted triples
#pragma unroll
    for (int o = 16; o; o >>= 1) {
        float a0 = __shfl_down_sync(0xffffffffu, t.d0, o);
        float a1 = __shfl_down_sync(0xffffffffu, t.d1, o);
        float a2 = __shfl_down_sync(0xffffffffu, t.d2, o);
        int   b0 = __shfl_down_sync(0xffffffffu, t.i0, o);
        int   b1 = __shfl_down_sync(0xffffffffu, t.i1, o);
        int   b2 = __shfl_down_sync(0xffffffffu, t.i2, o);
        t3_ins(t, a0, b0); t3_ins(t, a1, b1); t3_ins(t, a2, b2);
    }

    __shared__ float sd[8][3];
    __shared__ int   si[8][3];
    __shared__ float sw[3];
    __shared__ int   sidx[3];

    if ((threadIdx.x & 31) == 0) {
        int w = threadIdx.x >> 5;
        sd[w][0] = t.d0; sd[w][1] = t.d1; sd[w][2] = t.d2;
        si[w][0] = t.i0; si[w][1] = t.i1; si[w][2] = t.i2;
    }
    __syncthreads();

    if (threadIdx.x == 0) {
        T3 f;
        f.d0 = sd[0][0]; f.d1 = sd[0][1]; f.d2 = sd[0][2];
        f.i0 = si[0][0]; f.i1 = si[0][1]; f.i2 = si[0][2];
        for (int w = 1; w < 8; w++) {
            t3_ins(f, sd[w][0], si[w][0]);
            t3_ins(f, sd[w][1], si[w][1]);
            t3_ins(f, sd[w][2], si[w][2]);
        }
        float e0 = sqrtf(fmaxf(f.d0, 1e-12f));
        float e1 = sqrtf(fmaxf(f.d1, 1e-12f));
        float e2 = sqrtf(fmaxf(f.d2, 1e-12f));
        // softmax over (-e0,-e1,-e2); -e0 is the max
        float w0 = 1.f;
        float w1 = expf(e0 - e1);
        float w2 = expf(e0 - e2);
        float inv = 1.f / (w0 + w1 + w2);
        sw[0] = w0 * inv; sw[1] = w1 * inv; sw[2] = w2 * inv;
        sidx[0] = f.i0; sidx[1] = f.i1; sidx[2] = f.i2;
    }
    __syncthreads();

    if (threadIdx.x < ED) {
        int e = threadIdx.x;
        float r = sw[0] * V[(size_t)sidx[0] * ED + e]
                + sw[1] * V[(size_t)sidx[1] * ED + e]
                + sw[2] * V[(size_t)sidx[2] * ED + e];
        out[(size_t)n * ED + e] = r;
    }
}

// ---------------- launch -----------------------------------------------------
extern "C" void kernel_launch(void* const* d_in, const int* in_sizes, int n_in,
                              void* d_out, int out_size)
{
    const float* x    = (const float*)d_in[0];  // [8192, 5120]
    const float* keys = (const float*)d_in[1];  // [8192, 5120]
    const float* vals = (const float*)d_in[2];  // [8192, 128]
    const float* wkey = (const float*)d_in[3];  // [1280, 5120]
    float* out = (float*)d_out;                 // [8192, 128]

    float *proj, *nrm, *dd;
    cudaGetSymbolAddress((void**)&proj, g_proj);
    cudaGetSymbolAddress((void**)&nrm,  g_norm);
    cudaGetSymbolAddress((void**)&dd,   g_d2);

    float* projK = proj + (size_t)NQ * PD;

    dim3 gProj(PD / 128, NQ / 128);   // (10, 64)
    sgemm_nt<0><<<gProj, 256>>>(x,    wkey, proj,  HD, PD, nullptr, nullptr);
    sgemm_nt<0><<<gProj, 256>>>(keys, wkey, projK, HD, PD, nullptr, nullptr);

    row_norms<<<NQ + MM, 128>>>(proj, nrm);

    dim3 gDist(MM / 128, NQ / 128);   // (64, 64)
    sgemm_nt<1><<<gDist, 256>>>(proj, projK, dd, PD, MM, nrm, nrm + NQ);

    topk_out<<<NQ, 256>>>(dd, vals, out);
}

// round 14
// speedup vs baseline: 2.2059x; 2.2059x over previous
#include <cuda_runtime.h>
#include <cuda_bf16.h>
#include <cstdint>

#define NQ 8192
#define MM 8192
#define HD 5120
#define PD 1280
#define ED 128

// ---------------- scratch (allocation-free) ----------------------------------
__device__ float g_proj[(size_t)(NQ + MM) * PD];
__device__ float g_norm[NQ + MM];
__device__ float g_d2[(size_t)NQ * MM];

// ---------------- PTX helpers (base sm_103 features only) --------------------
__device__ __forceinline__ uint32_t smem_u32(const void* p) {
    uint32_t a;
    asm("{ .reg .u64 t; cvta.to.shared.u64 t, %1; cvt.u32.u64 %0, t; }" : "=r"(a) : "l"(p));
    return a;
}
__device__ __forceinline__ void ldm4(uint32_t* r, uint32_t addr) {
    asm volatile("ldmatrix.sync.aligned.m8n8.x4.shared.b16 {%0,%1,%2,%3}, [%4];"
                 : "=r"(r[0]), "=r"(r[1]), "=r"(r[2]), "=r"(r[3]) : "r"(addr));
}
__device__ __forceinline__ void mma16816(float* c, const uint32_t* a, const uint32_t* b) {
    asm volatile("mma.sync.aligned.m16n8k16.row.col.f32.bf16.bf16.f32 "
                 "{%0,%1,%2,%3}, {%4,%5,%6,%7}, {%8,%9}, {%0,%1,%2,%3};"
                 : "+f"(c[0]), "+f"(c[1]), "+f"(c[2]), "+f"(c[3])
                 : "r"(a[0]), "r"(a[1]), "r"(a[2]), "r"(a[3]), "r"(b[0]), "r"(b[1]));
}
// pack two fp32 -> bf16x2 (x -> low half, y -> high half)
__device__ __forceinline__ uint32_t packbf(float x, float y) {
    uint32_t r;
    asm("cvt.rn.bf16x2.f32 %0, %1, %2;" : "=r"(r) : "f"(y), "f"(x));
    return r;
}

// swizzled byte offset inside one 128x32 bf16 tile (64B rows, 4x16B chunks)
__device__ __forceinline__ uint32_t swz(int row, int chunk) {
    return (uint32_t)(row * 64 + ((chunk ^ ((row >> 1) & 3)) * 16));
}

// smem layout per stage: Ah | Al | Bh | Bl, each 128x32 bf16 = 8192 B
#define T_SZ   8192
#define STG_SZ (4 * T_SZ)
#define SMEM_BYTES (2 * STG_SZ)   // 65536

// ---------------- hi/lo split fill: fp32 -> two bf16 tiles -------------------
__device__ __forceinline__ void cvt_store(char* hi, char* lo, const float4* v, int tid)
{
#pragma unroll
    for (int i = 0; i < 4; ++i) {
        const int idx = i * 256 + tid;          // 1024 float4 = 128 rows x 8
        const int row = idx >> 3;
        const int c4  = idx & 7;
        const float4 x = v[i];
        const uint32_t h01 = packbf(x.x, x.y);
        const uint32_t h23 = packbf(x.z, x.w);
        const float f0 = __uint_as_float(h01 << 16);
        const float f1 = __uint_as_float(h01 & 0xffff0000u);
        const float f2 = __uint_as_float(h23 << 16);
        const float f3 = __uint_as_float(h23 & 0xffff0000u);
        const uint32_t l01 = packbf(x.x - f0, x.y - f1);
        const uint32_t l23 = packbf(x.z - f2, x.w - f3);
        const uint32_t off = swz(row, c4 >> 1) + (c4 & 1) * 8;
        *(uint2*)(hi + off) = make_uint2(h01, h23);
        *(uint2*)(lo + off) = make_uint2(l01, l23);
    }
}
__device__ __forceinline__ void ld_tile(float4* v, const float* __restrict__ G,
                                        int ldg, int row0, int k0, int tid)
{
#pragma unroll
    for (int i = 0; i < 4; ++i) {
        const int idx = i * 256 + tid;
        const int row = idx >> 3;
        const int c4  = idx & 7;
        v[i] = *(const float4*)(G + (size_t)(row0 + row) * ldg + (k0 + c4 * 4));
    }
}

// ---------------- HMMA split-bf16 NT GEMM ------------------------------------
// C[i,j] = sum_k A[i,k]*B[j,k] with fp32-accurate hi/lo split (3 passes).
// DIST=1: C = nA[i] + nB[j] - 2*dot
template <int DIST>
__global__ __launch_bounds__(256, 2)
void gemm_hmma(const float* __restrict__ A, const float* __restrict__ B,
               float* __restrict__ C, int K, int ldc,
               const float* __restrict__ nA, const float* __restrict__ nB)
{
    extern __shared__ char smem[];
    const uint32_t sb = smem_u32(smem);

    const int tid = threadIdx.x;
    const int wid = tid >> 5;
    const int lane = tid & 31;
    const int warp_m = wid & 3;          // 4 warps over M
    const int warp_n = wid >> 2;         // 2 warps over N
    const int brow = blockIdx.y * 128;
    const int bcol = blockIdx.x * 128;

    float acc[2][8][4];
#pragma unroll
    for (int mt = 0; mt < 2; ++mt)
#pragma unroll
        for (int nt = 0; nt < 8; ++nt)
#pragma unroll
            for (int q = 0; q < 4; ++q) acc[mt][nt][q] = 0.f;

    const int nchunk = K >> 5;

    // prologue: fill stage 0 (chunk 0)
    {
        float4 va[4], vb[4];
        ld_tile(va, A, K, brow, 0, tid);
        ld_tile(vb, B, K, bcol, 0, tid);
        cvt_store(smem + 0 * T_SZ, smem + 1 * T_SZ, va, tid);
        cvt_store(smem + 2 * T_SZ, smem + 3 * T_SZ, vb, tid);
    }
    __syncthreads();

    // precomputed ldmatrix lane-address components
    const int a_row  = warp_m * 32 + (lane & 15);       // + mt*16
    const int a_chk  = lane >> 4;                        // + 2*ks
    const int b_row  = warp_n * 64 + ((lane >> 4) * 8) + (lane & 7);  // + p*16
    const int b_chk  = (lane >> 3) & 1;                  // + 2*ks

    for (int c = 0; c < nchunk; ++c) {
        const int s = c & 1;
        const uint32_t st = sb + s * STG_SZ;

        float4 va[4], vb[4];
        if (c + 1 < nchunk) {
            const int k0 = (c + 1) << 5;
            ld_tile(va, A, K, brow, k0, tid);
            ld_tile(vb, B, K, bcol, k0, tid);
        }

#pragma unroll
        for (int ks = 0; ks < 2; ++ks) {
            uint32_t ah[2][4], al[2][4], bb[4][4];
            // load A-hi fragments
#pragma unroll
            for (int mt = 0; mt < 2; ++mt)
                ldm4(ah[mt], st + 0 * T_SZ + swz(a_row + mt * 16, 2 * ks + a_chk));
            // load B-hi fragments (4 pairs -> 8 n-tiles)
#pragma unroll
            for (int p = 0; p < 4; ++p)
                ldm4(bb[p], st + 2 * T_SZ + swz(b_row + p * 16, 2 * ks + b_chk));
            // pass 1: Ah * Bh
#pragma unroll
            for (int mt = 0; mt < 2; ++mt)
#pragma unroll
                for (int nt = 0; nt < 8; ++nt)
                    mma16816(acc[mt][nt], ah[mt], &bb[nt >> 1][(nt & 1) * 2]);
            // load A-lo, pass 2: Al * Bh
#pragma unroll
            for (int mt = 0; mt < 2; ++mt)
                ldm4(al[mt], st + 1 * T_SZ + swz(a_row + mt * 16, 2 * ks + a_chk));
#pragma unroll
            for (int mt = 0; mt < 2; ++mt)
#pragma unroll
                for (int nt = 0; nt < 8; ++nt)
                    mma16816(acc[mt][nt], al[mt], &bb[nt >> 1][(nt & 1) * 2]);
            // load B-lo (reuse regs), pass 3: Ah * Bl
#pragma unroll
            for (int p = 0; p < 4; ++p)
                ldm4(bb[p], st + 3 * T_SZ + swz(b_row + p * 16, 2 * ks + b_chk));
#pragma unroll
            for (int mt = 0; mt < 2; ++mt)
#pragma unroll
                for (int nt = 0; nt < 8; ++nt)
                    mma16816(acc[mt][nt], ah[mt], &bb[nt >> 1][(nt & 1) * 2]);
        }

        if (c + 1 < nchunk) {
            char* st2 = smem + (s ^ 1) * STG_SZ;
            cvt_store(st2 + 0 * T_SZ, st2 + 1 * T_SZ, va, tid);
            cvt_store(st2 + 2 * T_SZ, st2 + 3 * T_SZ, vb, tid);
        }
        __syncthreads();
    }

    // epilogue: fragment (row l/4 [+8], col 2*(l%4))
#pragma unroll
    for (int mt = 0; mt < 2; ++mt) {
        const int r0 = brow + warp_m * 32 + mt * 16 + (lane >> 2);
        float na0 = 0.f, na1 = 0.f;
        if (DIST) { na0 = nA[r0]; na1 = nA[r0 + 8]; }
#pragma unroll
        for (int nt = 0; nt < 8; ++nt) {
            const int cc = bcol + warp_n * 64 + nt * 8 + (lane & 3) * 2;
            float v0 = acc[mt][nt][0], v1 = acc[mt][nt][1];
            float v2 = acc[mt][nt][2], v3 = acc[mt][nt][3];
            if (DIST) {
                const float2 nb = *(const float2*)(nB + cc);
                v0 = na0 + nb.x - 2.f * v0;
                v1 = na0 + nb.y - 2.f * v1;
                v2 = na1 + nb.x - 2.f * v2;
                v3 = na1 + nb.y - 2.f * v3;
            }
            *(float2*)(C + (size_t)r0 * ldc + cc)       = make_float2(v0, v1);
            *(float2*)(C + (size_t)(r0 + 8) * ldc + cc) = make_float2(v2, v3);
        }
    }
}

// ---------------- squared row norms ------------------------------------------
__global__ void row_norms(const float* __restrict__ X, float* __restrict__ nrm)
{
    const int row = blockIdx.x;
    const float4* p = (const float4*)(X + (size_t)row * PD);
    float s = 0.f;
    for (int i = threadIdx.x; i < PD / 4; i += blockDim.x) {
        float4 v = p[i];
        s += v.x * v.x + v.y * v.y + v.z * v.z + v.w * v.w;
    }
#pragma unroll
    for (int o = 16; o; o >>= 1) s += __shfl_down_sync(0xffffffffu, s, o);
    __shared__ float red[4];
    if ((threadIdx.x & 31) == 0) red[threadIdx.x >> 5] = s;
    __syncthreads();
    if (threadIdx.x == 0) nrm[row] = red[0] + red[1] + red[2] + red[3];
}

// ---------------- top-3 + softmax + gather-weighted-sum ----------------------
struct T3 { float d0, d1, d2; int i0, i1, i2; };

__device__ __forceinline__ void t3_ins(T3& t, float d, int m)
{
    if (d < t.d2) {
        if (d < t.d1) {
            t.d2 = t.d1; t.i2 = t.i1;
            if (d < t.d0) { t.d1 = t.d0; t.i1 = t.i0; t.d0 = d; t.i0 = m; }
            else          { t.d1 = d;    t.i1 = m; }
        } else {
            t.d2 = d; t.i2 = m;
        }
    }
}

__global__ __launch_bounds__(256)
void topk_out(const float* __restrict__ D2, const float* __restrict__ V,
              float* __restrict__ out)
{
    const int n = blockIdx.x;
    const float* drow = D2 + (size_t)n * MM;

    T3 t;
    t.d0 = t.d1 = t.d2 = 1e30f;
    t.i0 = t.i1 = t.i2 = 0;
    for (int m = threadIdx.x; m < MM; m += 256) t3_ins(t, drow[m], m);

#pragma unroll
    for (int o = 16; o; o >>= 1) {
        float a0 = __shfl_down_sync(0xffffffffu, t.d0, o);
        float a1 = __shfl_down_sync(0xffffffffu, t.d1, o);
        float a2 = __shfl_down_sync(0xffffffffu, t.d2, o);
        int   b0 = __shfl_down_sync(0xffffffffu, t.i0, o);
        int   b1 = __shfl_down_sync(0xffffffffu, t.i1, o);
        int   b2 = __shfl_down_sync(0xffffffffu, t.i2, o);
        t3_ins(t, a0, b0); t3_ins(t, a1, b1); t3_ins(t, a2, b2);
    }

    __shared__ float sd[8][3];
    __shared__ int   si[8][3];
    __shared__ float sw[3];
    __shared__ int   sidx[3];

    if ((threadIdx.x & 31) == 0) {
        int w = threadIdx.x >> 5;
        sd[w][0] = t.d0; sd[w][1] = t.d1; sd[w][2] = t.d2;
        si[w][0] = t.i0; si[w][1] = t.i1; si[w][2] = t.i2;
    }
    __syncthreads();

    if (threadIdx.x == 0) {
        T3 f;
        f.d0 = sd[0][0]; f.d1 = sd[0][1]; f.d2 = sd[0][2];
        f.i0 = si[0][0]; f.i1 = si[0][1]; f.i2 = si[0][2];
        for (int w = 1; w < 8; w++) {
            t3_ins(f, sd[w][0], si[w][0]);
            t3_ins(f, sd[w][1], si[w][1]);
            t3_ins(f, sd[w][2], si[w][2]);
        }
        float e0 = sqrtf(fmaxf(f.d0, 1e-12f));
        float e1 = sqrtf(fmaxf(f.d1, 1e-12f));
        float e2 = sqrtf(fmaxf(f.d2, 1e-12f));
        float w0 = 1.f;
        float w1 = expf(e0 - e1);
        float w2 = expf(e0 - e2);
        float inv = 1.f / (w0 + w1 + w2);
        sw[0] = w0 * inv; sw[1] = w1 * inv; sw[2] = w2 * inv;
        sidx[0] = f.i0; sidx[1] = f.i1; sidx[2] = f.i2;
    }
    __syncthreads();

    if (threadIdx.x < ED) {
        int e = threadIdx.x;
        float r = sw[0] * V[(size_t)sidx[0] * ED + e]
                + sw[1] * V[(size_t)sidx[1] * ED + e]
                + sw[2] * V[(size_t)sidx[2] * ED + e];
        out[(size_t)n * ED + e] = r;
    }
}

// ---------------- launch -----------------------------------------------------
extern "C" void kernel_launch(void* const* d_in, const int* in_sizes, int n_in,
                              void* d_out, int out_size)
{
    const float* x    = (const float*)d_in[0];  // [8192, 5120]
    const float* keys = (const float*)d_in[1];  // [8192, 5120]
    const float* vals = (const float*)d_in[2];  // [8192, 128]
    const float* wkey = (const float*)d_in[3];  // [1280, 5120]
    float* out = (float*)d_out;                 // [8192, 128]

    float *proj, *nrm, *dd;
    cudaGetSymbolAddress((void**)&proj, g_proj);
    cudaGetSymbolAddress((void**)&nrm,  g_norm);
    cudaGetSymbolAddress((void**)&dd,   g_d2);

    float* projK = proj + (size_t)NQ * PD;

    cudaFuncSetAttribute(gemm_hmma<0>, cudaFuncAttributeMaxDynamicSharedMemorySize, SMEM_BYTES);
    cudaFuncSetAttribute(gemm_hmma<1>, cudaFuncAttributeMaxDynamicSharedMemorySize, SMEM_BYTES);

    dim3 gProj(PD / 128, NQ / 128);   // (10, 64)
    gemm_hmma<0><<<gProj, 256, SMEM_BYTES>>>(x,    wkey, proj,  HD, PD, nullptr, nullptr);
    gemm_hmma<0><<<gProj, 256, SMEM_BYTES>>>(keys, wkey, projK, HD, PD, nullptr, nullptr);

    row_norms<<<NQ + MM, 128>>>(proj, nrm);

    dim3 gDist(MM / 128, NQ / 128);   // (64, 64)
    gemm_hmma<1><<<gDist, 256, SMEM_BYTES>>>(proj, projK, dd, PD, MM, nrm, nrm + NQ);

    topk_out<<<NQ, 256>>>(dd, vals, out);
}